// round 1
// baseline (speedup 1.0000x reference)
#include <cuda_runtime.h>
#include <cstdint>

#define NN   4096
#define FIN  256
#define NH   4
#define DHH  64

// Intermediates (device globals; no allocation allowed)
__device__ float g_h[NH * NN * DHH];     // h[head][n][d]
__device__ float g_ssrc[NH * NN];
__device__ float g_sdst[NH * NN];

// ---------------------------------------------------------------------------
// Kernel 1: h[head][n][d] = sum_f x[n][f] * W[head][f][d]
// Tile 64n x 64d, K-chunks of 64, 256 threads, 4x4 micro-tile.
// ---------------------------------------------------------------------------
__global__ __launch_bounds__(256) void k1_hproj(const float* __restrict__ x,
                                                const float* __restrict__ W) {
    __shared__ float xs[64][68];   // [f_local][n_local]  (transposed x tile)
    __shared__ float ws[64][68];   // [f_local][d]
    const int head = blockIdx.x;
    const int n0   = blockIdx.y * 64;
    const int tid  = threadIdx.x;
    const int tx   = tid & 15;     // d group
    const int ty   = tid >> 4;     // n group
    const float* Wh = W + (size_t)head * FIN * DHH;

    float c[4][4] = {};

    for (int f0 = 0; f0 < FIN; f0 += 64) {
        __syncthreads();
#pragma unroll
        for (int r = 0; r < 4; r++) {
            int idx = tid + r * 256;       // 0..1023 float4 slots
            int row = idx >> 4;            // 0..63
            int c4  = idx & 15;
            float4 v = *(const float4*)(x + (size_t)(n0 + row) * FIN + f0 + c4 * 4);
            xs[c4 * 4 + 0][row] = v.x;
            xs[c4 * 4 + 1][row] = v.y;
            xs[c4 * 4 + 2][row] = v.z;
            xs[c4 * 4 + 3][row] = v.w;
            float4 wv = *(const float4*)(Wh + (size_t)(f0 + row) * DHH + c4 * 4);
            *(float4*)&ws[row][c4 * 4] = wv;
        }
        __syncthreads();
#pragma unroll 16
        for (int k = 0; k < 64; k++) {
            float4 avv = *(const float4*)&xs[k][ty * 4];
            float4 bvv = *(const float4*)&ws[k][tx * 4];
            const float aa[4] = {avv.x, avv.y, avv.z, avv.w};
            const float bb[4] = {bvv.x, bvv.y, bvv.z, bvv.w};
#pragma unroll
            for (int ii = 0; ii < 4; ii++)
#pragma unroll
                for (int jj = 0; jj < 4; jj++)
                    c[ii][jj] = fmaf(aa[ii], bb[jj], c[ii][jj]);
        }
    }

    float* hout = g_h + ((size_t)head * NN + n0) * DHH;
#pragma unroll
    for (int ii = 0; ii < 4; ii++) {
        *(float4*)(hout + (size_t)(ty * 4 + ii) * DHH + tx * 4) =
            make_float4(c[ii][0], c[ii][1], c[ii][2], c[ii][3]);
    }
}

// ---------------------------------------------------------------------------
// Kernel 2: s_src[h][n] = h[h][n][:] . a1[h],  s_dst = h . a2[h]
// One warp per node; 8 nodes per 256-thread block.
// ---------------------------------------------------------------------------
__global__ __launch_bounds__(256) void k2_scores(const float* __restrict__ a) {
    const int head = blockIdx.x;
    const int lane = threadIdx.x & 31;
    const int warp = threadIdx.x >> 5;
    const int n    = blockIdx.y * 8 + warp;
    const float* hv = g_h + ((size_t)head * NN + n) * DHH;
    const float* ah = a + head * 2 * DHH;

    float h0 = hv[lane];
    float h1 = hv[lane + 32];
    float s1 = h0 * ah[lane] + h1 * ah[lane + 32];
    float s2 = h0 * ah[64 + lane] + h1 * ah[96 + lane];
#pragma unroll
    for (int o = 16; o; o >>= 1) {
        s1 += __shfl_xor_sync(0xffffffffu, s1, o);
        s2 += __shfl_xor_sync(0xffffffffu, s2, o);
    }
    if (lane == 0) {
        g_ssrc[head * NN + n] = s1;
        g_sdst[head * NN + n] = s2;
    }
}

// ---------------------------------------------------------------------------
// Kernel 3: fused masked-softmax attention aggregation + ELU.
//   P_ij = adj_ij ? exp(leaky_relu(s_i + t_j)) : 0      (no max pass needed:
//   leaky_relu bounds e to ~[-0.15, +10]; exp cannot overflow fp32)
//   out[i][head*64+d] = elu( (sum_j P_ij h_jd) / (sum_j P_ij) )
//
// Block = one head x 32 i-rows, 128 threads.
// j-tiles of 64: stage h-tile + t + P-tile in smem, then a register-tiled
// P@h GEMM phase using packed fma.rn.f32x2 (FFMA2): thread = 1 row x 16 d.
// ---------------------------------------------------------------------------
#define TI 32
#define TJ 64

__global__ __launch_bounds__(128, 4) void k3_agg(const int* __restrict__ adj,
                                                 float* __restrict__ out) {
    __shared__ float sh_h[TJ][DHH];          // 16 KB, pitch 64 floats (256B)
    __shared__ float sh_P[TI][TJ + 4];       // 8.7 KB
    __shared__ float sh_t[TJ];

    const int head = blockIdx.x;             // fastest dim: heads share adj via L2
    const int i0   = blockIdx.y * TI;
    const int tid  = threadIdx.x;
    const int lane = tid & 31;
    const int warp = tid >> 5;
    const int i_loc = tid >> 2;              // 0..31: output row
    const int dgrp  = tid & 3;               // 0..3 : 16 d per thread
    const float* hbase = g_h + (size_t)head * NN * DHH;

    // s_src for the 8 rows this warp handles in the P phase
    float s_i[8];
#pragma unroll
    for (int ii = 0; ii < 8; ii++)
        s_i[ii] = g_ssrc[head * NN + i0 + warp * 8 + ii];

    float rs[8] = {};                        // per-lane partial rowsums
    unsigned long long acc[8] = {};          // 8 packed f32x2 accumulators (16 d)
    const unsigned hsm =
        (unsigned)__cvta_generic_to_shared(&sh_h[0][0]) + dgrp * 64;

    for (int j0 = 0; j0 < NN; j0 += TJ) {
        __syncthreads();
        // stage h tile [TJ][64] (coalesced float4)
#pragma unroll
        for (int r = 0; r < 8; r++) {
            int idx = tid + r * 128;         // 1024 float4 slots
            int row = idx >> 4;
            int c4  = idx & 15;
            *(float4*)&sh_h[row][c4 * 4] =
                *(const float4*)(hbase + (size_t)(j0 + row) * DHH + c4 * 4);
        }
        if (tid < TJ) sh_t[tid] = g_sdst[head * NN + j0 + tid];
        __syncthreads();

        // ---- P phase: each warp computes 8 rows of P over this j-tile ----
#pragma unroll
        for (int ii = 0; ii < 8; ii++) {
            const int i = i0 + warp * 8 + ii;
            const int* arow = adj + (size_t)i * NN + j0;
            const float si = s_i[ii];
#pragma unroll
            for (int k = 0; k < TJ / 32; k++) {
                const int jj = lane + k * 32;
                const float z = si + sh_t[jj];
                const float e = z > 0.f ? z : 0.01f * z;
                const float p = arow[jj] ? __expf(e) : 0.f;
                sh_P[warp * 8 + ii][jj] = p;
                rs[ii] += p;
            }
        }
        __syncthreads();

        // ---- GEMM phase: acc[i_loc][16d] += P[i_loc][j] * h[j][16d] ----
#pragma unroll 8
        for (int j = 0; j < TJ; j++) {
            const float p = sh_P[i_loc][j];
            union { float2 f; unsigned long long u; } pp;
            pp.f.x = p; pp.f.y = p;
            unsigned long long h0, h1, h2, h3, h4, h5, h6, h7;
            const unsigned addr = hsm + j * 256;
            asm volatile(
                "ld.shared.v2.b64 {%0,%1},[%8];\n\t"
                "ld.shared.v2.b64 {%2,%3},[%8+16];\n\t"
                "ld.shared.v2.b64 {%4,%5},[%8+32];\n\t"
                "ld.shared.v2.b64 {%6,%7},[%8+48];"
                : "=l"(h0), "=l"(h1), "=l"(h2), "=l"(h3),
                  "=l"(h4), "=l"(h5), "=l"(h6), "=l"(h7)
                : "r"(addr));
            asm("fma.rn.f32x2 %0, %1, %2, %0;" : "+l"(acc[0]) : "l"(pp.u), "l"(h0));
            asm("fma.rn.f32x2 %0, %1, %2, %0;" : "+l"(acc[1]) : "l"(pp.u), "l"(h1));
            asm("fma.rn.f32x2 %0, %1, %2, %0;" : "+l"(acc[2]) : "l"(pp.u), "l"(h2));
            asm("fma.rn.f32x2 %0, %1, %2, %0;" : "+l"(acc[3]) : "l"(pp.u), "l"(h3));
            asm("fma.rn.f32x2 %0, %1, %2, %0;" : "+l"(acc[4]) : "l"(pp.u), "l"(h4));
            asm("fma.rn.f32x2 %0, %1, %2, %0;" : "+l"(acc[5]) : "l"(pp.u), "l"(h5));
            asm("fma.rn.f32x2 %0, %1, %2, %0;" : "+l"(acc[6]) : "l"(pp.u), "l"(h6));
            asm("fma.rn.f32x2 %0, %1, %2, %0;" : "+l"(acc[7]) : "l"(pp.u), "l"(h7));
        }
    }

    // ---- rowsum reduction: every lane gets totals for all 8 warp rows ----
#pragma unroll
    for (int ii = 0; ii < 8; ii++)
#pragma unroll
        for (int o = 16; o; o >>= 1)
            rs[ii] += __shfl_xor_sync(0xffffffffu, rs[ii], o);

    const int im = lane >> 2;                // which of the warp's 8 rows is mine
    float rstot = rs[0];
    if (im == 1) rstot = rs[1];
    if (im == 2) rstot = rs[2];
    if (im == 3) rstot = rs[3];
    if (im == 4) rstot = rs[4];
    if (im == 5) rstot = rs[5];
    if (im == 6) rstot = rs[6];
    if (im == 7) rstot = rs[7];
    const float inv = 1.0f / rstot;

    float* orow = out + (size_t)(i0 + i_loc) * (NH * DHH) + head * DHH + dgrp * 16;
#pragma unroll
    for (int q = 0; q < 4; q++) {
        union { float2 f; unsigned long long u; } u0, u1;
        u0.u = acc[2 * q];
        u1.u = acc[2 * q + 1];
        float v0 = u0.f.x * inv;
        float v1 = u0.f.y * inv;
        float v2 = u1.f.x * inv;
        float v3 = u1.f.y * inv;
        v0 = v0 > 0.f ? v0 : expm1f(v0);
        v1 = v1 > 0.f ? v1 : expm1f(v1);
        v2 = v2 > 0.f ? v2 : expm1f(v2);
        v3 = v3 > 0.f ? v3 : expm1f(v3);
        *(float4*)(orow + q * 4) = make_float4(v0, v1, v2, v3);
    }
}

// ---------------------------------------------------------------------------
extern "C" void kernel_launch(void* const* d_in, const int* in_sizes, int n_in,
                              void* d_out, int out_size) {
    (void)in_sizes; (void)n_in; (void)out_size;
    const float* x   = (const float*)d_in[0];
    const int*   adj = (const int*)d_in[1];
    const float* W   = (const float*)d_in[2];
    const float* a   = (const float*)d_in[3];
    float* out = (float*)d_out;

    k1_hproj<<<dim3(NH, NN / 64), 256>>>(x, W);
    k2_scores<<<dim3(NH, NN / 8), 256>>>(a);
    k3_agg<<<dim3(NH, NN / TI), 128>>>(adj, out);
}

// round 3
// speedup vs baseline: 5.5842x; 5.5842x over previous
#include <cuda_runtime.h>
#include <cstdint>

#define NN   4096
#define FIN  256
#define NH   4
#define DHH  64
#define NW   (NN / 32)      // 128 adj-mask words per row

// ------------------------- device globals (no alloc allowed) ---------------
__device__ float g_h [NH * NN * DHH];     // h[head][n][d]
__device__ float g_hT[NH * DHH * NN];     // hT[head][d][n]
__device__ float g_ssrc[NH * NN];
__device__ float g_sdst[NH * NN];
__device__ float g_E[NH * NN];            // exp(s_src)
__device__ float g_e[NH * NN];            // exp(0.01*s_src)
__device__ float g_F[NH * NN];            // exp(s_dst)
__device__ float g_f[NH * NN];            // exp(0.01*s_dst)
__device__ unsigned g_adjm[NN * NW];      // adjacency bitmask

// ------------------------- helpers -----------------------------------------
__device__ __forceinline__ uint32_t smem_u32(const void* p) {
    uint32_t a;
    asm("{ .reg .u64 t; cvta.to.shared.u64 t, %1; cvt.u32.u64 %0, t; }"
        : "=r"(a) : "l"(p));
    return a;
}
__device__ __forceinline__ uint32_t f2tf(float x) {   // round-to-nearest tf32
    uint32_t u;
    asm("cvt.rna.tf32.f32 %0, %1;" : "=r"(u) : "f"(x));
    return u;
}
#define LDSM4(r0, r1, r2, r3, addr) \
    asm volatile("ldmatrix.sync.aligned.m8n8.x4.shared.b16 {%0,%1,%2,%3}, [%4];" \
                 : "=r"(r0), "=r"(r1), "=r"(r2), "=r"(r3) : "r"(addr))
#define MMA_TF32(c, a0, a1, a2, a3, b0, b1) \
    asm volatile("mma.sync.aligned.m16n8k8.row.col.f32.tf32.tf32.f32 " \
                 "{%0,%1,%2,%3}, {%4,%5,%6,%7}, {%8,%9}, {%0,%1,%2,%3};" \
                 : "+f"((c)[0]), "+f"((c)[1]), "+f"((c)[2]), "+f"((c)[3]) \
                 : "r"(a0), "r"(a1), "r"(a2), "r"(a3), "r"(b0), "r"(b1))

// ---------------------------------------------------------------------------
// Kernel 0: pack adj (0/1 int32) into bitmask words. One word per thread.
// ---------------------------------------------------------------------------
__global__ __launch_bounds__(256) void k0_pack(const int* __restrict__ adj) {
    const int widx = blockIdx.x * 256 + threadIdx.x;   // 0 .. NN*NW-1
    const int* p = adj + (size_t)widx * 32;
    unsigned m = 0;
#pragma unroll
    for (int q = 0; q < 8; q++) {
        int4 v = *(const int4*)(p + q * 4);
        m |= (v.x ? 1u : 0u) << (q * 4 + 0);
        m |= (v.y ? 1u : 0u) << (q * 4 + 1);
        m |= (v.z ? 1u : 0u) << (q * 4 + 2);
        m |= (v.w ? 1u : 0u) << (q * 4 + 3);
    }
    g_adjm[widx] = m;
}

// ---------------------------------------------------------------------------
// Kernel 1: h = x @ W per head; also writes hT[head][d][n].
// ---------------------------------------------------------------------------
__global__ __launch_bounds__(256) void k1_hproj(const float* __restrict__ x,
                                                const float* __restrict__ W) {
    __shared__ float xs[64][68];
    __shared__ float ws[64][68];
    const int head = blockIdx.x;
    const int n0   = blockIdx.y * 64;
    const int tid  = threadIdx.x;
    const int tx   = tid & 15;
    const int ty   = tid >> 4;
    const float* Wh = W + (size_t)head * FIN * DHH;

    float c[4][4] = {};
    for (int f0 = 0; f0 < FIN; f0 += 64) {
        __syncthreads();
#pragma unroll
        for (int r = 0; r < 4; r++) {
            int idx = tid + r * 256;
            int row = idx >> 4;
            int c4  = idx & 15;
            float4 v = *(const float4*)(x + (size_t)(n0 + row) * FIN + f0 + c4 * 4);
            xs[c4 * 4 + 0][row] = v.x;
            xs[c4 * 4 + 1][row] = v.y;
            xs[c4 * 4 + 2][row] = v.z;
            xs[c4 * 4 + 3][row] = v.w;
            *(float4*)&ws[row][c4 * 4] =
                *(const float4*)(Wh + (size_t)(f0 + row) * DHH + c4 * 4);
        }
        __syncthreads();
#pragma unroll 16
        for (int k = 0; k < 64; k++) {
            float4 av = *(const float4*)&xs[k][ty * 4];
            float4 bv = *(const float4*)&ws[k][tx * 4];
            const float aa[4] = {av.x, av.y, av.z, av.w};
            const float bb[4] = {bv.x, bv.y, bv.z, bv.w};
#pragma unroll
            for (int ii = 0; ii < 4; ii++)
#pragma unroll
                for (int jj = 0; jj < 4; jj++)
                    c[ii][jj] = fmaf(aa[ii], bb[jj], c[ii][jj]);
        }
    }
    float* hout = g_h + ((size_t)head * NN + n0) * DHH;
#pragma unroll
    for (int ii = 0; ii < 4; ii++)
        *(float4*)(hout + (size_t)(ty * 4 + ii) * DHH + tx * 4) =
            make_float4(c[ii][0], c[ii][1], c[ii][2], c[ii][3]);
    float* htb = g_hT + ((size_t)head * DHH) * NN + n0 + ty * 4;
#pragma unroll
    for (int jj = 0; jj < 4; jj++)
        *(float4*)(htb + (size_t)(tx * 4 + jj) * NN) =
            make_float4(c[0][jj], c[1][jj], c[2][jj], c[3][jj]);
}

// ---------------------------------------------------------------------------
// Kernel 2: scores + separable-exp tables.
// ---------------------------------------------------------------------------
__global__ __launch_bounds__(256) void k2_scores(const float* __restrict__ a) {
    const int head = blockIdx.x;
    const int lane = threadIdx.x & 31;
    const int warp = threadIdx.x >> 5;
    const int n    = blockIdx.y * 8 + warp;
    const float* hv = g_h + ((size_t)head * NN + n) * DHH;
    const float* ah = a + head * 2 * DHH;
    float h0 = hv[lane], h1 = hv[lane + 32];
    float s1 = h0 * ah[lane]      + h1 * ah[lane + 32];
    float s2 = h0 * ah[64 + lane] + h1 * ah[96 + lane];
#pragma unroll
    for (int o = 16; o; o >>= 1) {
        s1 += __shfl_xor_sync(0xffffffffu, s1, o);
        s2 += __shfl_xor_sync(0xffffffffu, s2, o);
    }
    if (lane == 0) {
        const int idx = head * NN + n;
        g_ssrc[idx] = s1;
        g_sdst[idx] = s2;
        g_E[idx] = __expf(s1);
        g_e[idx] = __expf(0.01f * s1);
        g_F[idx] = __expf(s2);
        g_f[idx] = __expf(0.01f * s2);
    }
}

// ---------------------------------------------------------------------------
// Kernel 3: masked-softmax aggregation + ELU via mma.sync tf32.
// CTA = 1 head x 128 i-rows, 256 threads (8 warps x 16i x 64d).
// K-tiles of 32 j: SIMT builds P[128][32] (separable exp, bitmask adj) and
// stages hT[64][32]; tensor pipe does D += P @ hT^T (4 k-steps of k8).
// Smem pitch 36 -> conflict-free ldmatrix.
// ---------------------------------------------------------------------------
#define TJ 32
#define NT (NN / TJ)

__global__ __launch_bounds__(256, 1) void k3_agg(float* __restrict__ out) {
    __shared__ float sP[128][36];
    __shared__ float sB[64][36];
    __shared__ float sRS[128];

    const int head = blockIdx.x;              // fastest: heads share hT/L2
    const int i0   = blockIdx.y * 128;
    const int tid  = threadIdx.x;
    const int lane = tid & 31;
    const int w    = tid >> 5;
    const int i    = tid >> 1;                // P-phase row 0..127
    const int jh   = (tid & 1) * 16;          // P-phase j-half

    const int rowg = head * NN + i0 + i;
    const float si = g_ssrc[rowg];
    const float Ei = g_E[rowg];
    const float ei = g_e[rowg];
    const float* tB = g_sdst + head * NN;
    const float* FB = g_F + head * NN;
    const float* fB = g_f + head * NN;
    const unsigned* mrow = g_adjm + (size_t)(i0 + i) * NW;
    const float* hT = g_hT + (size_t)head * DHH * NN;

    // ldmatrix lane addresses (pitch 36 words)
    const uint32_t sPu = smem_u32(&sP[0][0]);
    const uint32_t sBu = smem_u32(&sB[0][0]);
    const uint32_t aAddr = sPu +
        (((w * 16 + (lane & 15)) * 36 + (lane >> 4) * 4) << 2);
    const uint32_t bAddr = sBu +
        ((((lane >> 4) * 8 + (lane & 7)) * 36 + ((lane & 8) ? 4 : 0)) << 2);

    float c[8][4] = {};
    float rs = 0.f;

    for (int t = 0; t < NT; t++) {
        const int j0 = t * TJ;
        __syncthreads();
        // ---- stage hT tile [64][32] with tf32 rounding ----
#pragma unroll
        for (int r = 0; r < 2; r++) {
            int idx = tid + r * 256;          // 512 float4 slots
            int row = idx >> 3;
            int c4  = idx & 7;
            float4 v = *(const float4*)(hT + (size_t)row * NN + j0 + c4 * 4);
            uint4 u = make_uint4(f2tf(v.x), f2tf(v.y), f2tf(v.z), f2tf(v.w));
            *(uint4*)&sB[row][c4 * 4] = u;
        }
        // ---- P tile: 16 entries per thread, separable exp + bitmask ----
        const unsigned m = mrow[t] >> jh;
#pragma unroll
        for (int q = 0; q < 4; q++) {
            const int jb = j0 + jh + q * 4;
            float4 tv = *(const float4*)(tB + jb);
            float4 Fv = *(const float4*)(FB + jb);
            float4 fv = *(const float4*)(fB + jb);
            float z0 = si + tv.x, z1 = si + tv.y, z2 = si + tv.z, z3 = si + tv.w;
            float p0 = z0 > 0.f ? Ei * Fv.x : ei * fv.x;
            float p1 = z1 > 0.f ? Ei * Fv.y : ei * fv.y;
            float p2 = z2 > 0.f ? Ei * Fv.z : ei * fv.z;
            float p3 = z3 > 0.f ? Ei * Fv.w : ei * fv.w;
            p0 = (m >> (q * 4 + 0)) & 1u ? p0 : 0.f;
            p1 = (m >> (q * 4 + 1)) & 1u ? p1 : 0.f;
            p2 = (m >> (q * 4 + 2)) & 1u ? p2 : 0.f;
            p3 = (m >> (q * 4 + 3)) & 1u ? p3 : 0.f;
            rs += p0 + p1 + p2 + p3;
            uint4 u = make_uint4(f2tf(p0), f2tf(p1), f2tf(p2), f2tf(p3));
            *(uint4*)&sP[i][jh + q * 4] = u;
        }
        __syncthreads();
        // ---- tensor phase: 4 k-steps of m16n8k8 across 8 n-tiles ----
#pragma unroll
        for (int ks = 0; ks < 4; ks++) {
            uint32_t a0, a1, a2, a3;
            LDSM4(a0, a1, a2, a3, aAddr + ks * 32);
#pragma unroll
            for (int q2 = 0; q2 < 4; q2++) {
                uint32_t b0, b1, b2, b3;
                LDSM4(b0, b1, b2, b3, bAddr + q2 * 2304 + ks * 32);
                MMA_TF32(c[2 * q2],     a0, a1, a2, a3, b0, b1);
                MMA_TF32(c[2 * q2 + 1], a0, a1, a2, a3, b2, b3);
            }
        }
    }

    // ---- rowsums ----
    float rtot = rs + __shfl_xor_sync(0xffffffffu, rs, 1);
    if (!(tid & 1)) sRS[i] = rtot;
    __syncthreads();

    // ---- epilogue: normalize + ELU + store ----
    const int g  = lane >> 2;
    const int tg = lane & 3;
    const float inv0 = 1.0f / sRS[w * 16 + g];
    const float inv1 = 1.0f / sRS[w * 16 + g + 8];
    float* o0 = out + (size_t)(i0 + w * 16 + g) * (NH * DHH) + head * DHH;
    float* o1 = o0 + (size_t)8 * (NH * DHH);
#pragma unroll
    for (int nt = 0; nt < 8; nt++) {
        float v0 = c[nt][0] * inv0;
        float v1 = c[nt][1] * inv0;
        float v2 = c[nt][2] * inv1;
        float v3 = c[nt][3] * inv1;
        v0 = v0 > 0.f ? v0 : expm1f(v0);
        v1 = v1 > 0.f ? v1 : expm1f(v1);
        v2 = v2 > 0.f ? v2 : expm1f(v2);
        v3 = v3 > 0.f ? v3 : expm1f(v3);
        *(float2*)(o0 + nt * 8 + 2 * tg) = make_float2(v0, v1);
        *(float2*)(o1 + nt * 8 + 2 * tg) = make_float2(v2, v3);
    }
}

// ---------------------------------------------------------------------------
extern "C" void kernel_launch(void* const* d_in, const int* in_sizes, int n_in,
                              void* d_out, int out_size) {
    (void)in_sizes; (void)n_in; (void)out_size;
    const float* x   = (const float*)d_in[0];
    const int*   adj = (const int*)d_in[1];
    const float* W   = (const float*)d_in[2];
    const float* a   = (const float*)d_in[3];
    float* out = (float*)d_out;

    k0_pack <<<NN * NW / 256, 256>>>(adj);
    k1_hproj<<<dim3(NH, NN / 64), 256>>>(x, W);
    k2_scores<<<dim3(NH, NN / 8), 256>>>(a);
    k3_agg  <<<dim3(NH, NN / 128), 256>>>(out);
}

// round 4
// speedup vs baseline: 6.1268x; 1.0972x over previous
#include <cuda_runtime.h>
#include <cstdint>

#define NN   4096
#define FIN  256
#define NH   4
#define DHH  64
#define NW   (NN / 32)      // 128 adj-mask words per row

// ------------------------- device globals (no alloc allowed) ---------------
__device__ float g_h [NH * NN * DHH];     // h[head][n][d]
__device__ float g_hT[NH * DHH * NN];     // hT[head][d][n], tf32-rounded
__device__ float g_ssrc[NH * NN];
__device__ float g_sdst[NH * NN];
__device__ float g_E[NH * NN];            // exp(s_src)
__device__ float g_e[NH * NN];            // exp(0.01*s_src)
__device__ float g_F[NH * NN];            // exp(s_dst)
__device__ float g_f[NH * NN];            // exp(0.01*s_dst)
__device__ unsigned g_adjm[NN * NW];      // adjacency bitmask

// ------------------------- helpers -----------------------------------------
__device__ __forceinline__ uint32_t smem_u32(const void* p) {
    uint32_t a;
    asm("{ .reg .u64 t; cvta.to.shared.u64 t, %1; cvt.u32.u64 %0, t; }"
        : "=r"(a) : "l"(p));
    return a;
}
__device__ __forceinline__ uint32_t f2tf(float x) {   // round-to-nearest tf32
    uint32_t u;
    asm("cvt.rna.tf32.f32 %0, %1;" : "=r"(u) : "f"(x));
    return u;
}
#define LDSM4(r0, r1, r2, r3, addr) \
    asm volatile("ldmatrix.sync.aligned.m8n8.x4.shared.b16 {%0,%1,%2,%3}, [%4];" \
                 : "=r"(r0), "=r"(r1), "=r"(r2), "=r"(r3) : "r"(addr))
#define MMA_TF32(c, a0, a1, a2, a3, b0, b1) \
    asm volatile("mma.sync.aligned.m16n8k8.row.col.f32.tf32.tf32.f32 " \
                 "{%0,%1,%2,%3}, {%4,%5,%6,%7}, {%8,%9}, {%0,%1,%2,%3};" \
                 : "+f"((c)[0]), "+f"((c)[1]), "+f"((c)[2]), "+f"((c)[3]) \
                 : "r"(a0), "r"(a1), "r"(a2), "r"(a3), "r"(b0), "r"(b1))
#define CP_ASYNC16(dst, src) \
    asm volatile("cp.async.cg.shared.global [%0], [%1], 16;" \
                 :: "r"(dst), "l"(src) : "memory")
#define CP_COMMIT() asm volatile("cp.async.commit_group;" ::: "memory")
#define CP_WAIT(n)  asm volatile("cp.async.wait_group %0;" :: "n"(n) : "memory")

// ---------------------------------------------------------------------------
// Kernel 0: pack adj (0/1 int32) into bitmask words. One word per thread.
// ---------------------------------------------------------------------------
__global__ __launch_bounds__(256) void k0_pack(const int* __restrict__ adj) {
    const int widx = blockIdx.x * 256 + threadIdx.x;
    const int* p = adj + (size_t)widx * 32;
    unsigned m = 0;
#pragma unroll
    for (int q = 0; q < 8; q++) {
        int4 v = *(const int4*)(p + q * 4);
        m |= (v.x ? 1u : 0u) << (q * 4 + 0);
        m |= (v.y ? 1u : 0u) << (q * 4 + 1);
        m |= (v.z ? 1u : 0u) << (q * 4 + 2);
        m |= (v.w ? 1u : 0u) << (q * 4 + 3);
    }
    g_adjm[widx] = m;
}

// ---------------------------------------------------------------------------
// Kernel 1: h = x @ W per head; hT stored tf32-rounded for direct cp.async.
// ---------------------------------------------------------------------------
__global__ __launch_bounds__(256) void k1_hproj(const float* __restrict__ x,
                                                const float* __restrict__ W) {
    __shared__ float xs[64][68];
    __shared__ float ws[64][68];
    const int head = blockIdx.x;
    const int n0   = blockIdx.y * 64;
    const int tid  = threadIdx.x;
    const int tx   = tid & 15;
    const int ty   = tid >> 4;
    const float* Wh = W + (size_t)head * FIN * DHH;

    float c[4][4] = {};
    for (int f0 = 0; f0 < FIN; f0 += 64) {
        __syncthreads();
#pragma unroll
        for (int r = 0; r < 4; r++) {
            int idx = tid + r * 256;
            int row = idx >> 4;
            int c4  = idx & 15;
            float4 v = *(const float4*)(x + (size_t)(n0 + row) * FIN + f0 + c4 * 4);
            xs[c4 * 4 + 0][row] = v.x;
            xs[c4 * 4 + 1][row] = v.y;
            xs[c4 * 4 + 2][row] = v.z;
            xs[c4 * 4 + 3][row] = v.w;
            *(float4*)&ws[row][c4 * 4] =
                *(const float4*)(Wh + (size_t)(f0 + row) * DHH + c4 * 4);
        }
        __syncthreads();
#pragma unroll 16
        for (int k = 0; k < 64; k++) {
            float4 av = *(const float4*)&xs[k][ty * 4];
            float4 bv = *(const float4*)&ws[k][tx * 4];
            const float aa[4] = {av.x, av.y, av.z, av.w};
            const float bb[4] = {bv.x, bv.y, bv.z, bv.w};
#pragma unroll
            for (int ii = 0; ii < 4; ii++)
#pragma unroll
                for (int jj = 0; jj < 4; jj++)
                    c[ii][jj] = fmaf(aa[ii], bb[jj], c[ii][jj]);
        }
    }
    float* hout = g_h + ((size_t)head * NN + n0) * DHH;
#pragma unroll
    for (int ii = 0; ii < 4; ii++)
        *(float4*)(hout + (size_t)(ty * 4 + ii) * DHH + tx * 4) =
            make_float4(c[ii][0], c[ii][1], c[ii][2], c[ii][3]);
    float* htb = g_hT + ((size_t)head * DHH) * NN + n0 + ty * 4;
#pragma unroll
    for (int jj = 0; jj < 4; jj++) {
        uint4 u = make_uint4(f2tf(c[0][jj]), f2tf(c[1][jj]),
                             f2tf(c[2][jj]), f2tf(c[3][jj]));
        *(uint4*)(htb + (size_t)(tx * 4 + jj) * NN) = u;
    }
}

// ---------------------------------------------------------------------------
// Kernel 2: scores + separable-exp tables.
// ---------------------------------------------------------------------------
__global__ __launch_bounds__(256) void k2_scores(const float* __restrict__ a) {
    const int head = blockIdx.x;
    const int lane = threadIdx.x & 31;
    const int warp = threadIdx.x >> 5;
    const int n    = blockIdx.y * 8 + warp;
    const float* hv = g_h + ((size_t)head * NN + n) * DHH;
    const float* ah = a + head * 2 * DHH;
    float h0 = hv[lane], h1 = hv[lane + 32];
    float s1 = h0 * ah[lane]      + h1 * ah[lane + 32];
    float s2 = h0 * ah[64 + lane] + h1 * ah[96 + lane];
#pragma unroll
    for (int o = 16; o; o >>= 1) {
        s1 += __shfl_xor_sync(0xffffffffu, s1, o);
        s2 += __shfl_xor_sync(0xffffffffu, s2, o);
    }
    if (lane == 0) {
        const int idx = head * NN + n;
        g_ssrc[idx] = s1;
        g_sdst[idx] = s2;
        g_E[idx] = __expf(s1);
        g_e[idx] = __expf(0.01f * s1);
        g_F[idx] = __expf(s2);
        g_f[idx] = __expf(0.01f * s2);
    }
}

// ---------------------------------------------------------------------------
// Kernel 3: masked-softmax aggregation + ELU via mma.sync tf32.
// CTA = 1 head x 64 i-rows, 256 threads (8 warps = 4 i-groups x 2 d-halves,
// each 16i x 32d). j-tiles of 64; B tiles double-buffered via cp.async.
// ---------------------------------------------------------------------------
#define TJ 64
#define NT (NN / TJ)
#define PITCH 68
// dynamic smem layout (floats)
#define SP_OFF  0                       // sP[64][68]
#define SB_OFF  (64 * PITCH)            // sB[2][64][68]
#define RS_OFF  (SB_OFF + 2 * 64 * PITCH)
#define SMEM3   ((RS_OFF + 64) * 4)     // 52736 bytes

__global__ __launch_bounds__(256, 2) void k3_agg(float* __restrict__ out) {
    extern __shared__ float dsm[];
    float* sP  = dsm + SP_OFF;
    float* sB  = dsm + SB_OFF;
    float* sRS = dsm + RS_OFF;

    const int head = blockIdx.x;              // fastest: heads share adj rows
    const int i0   = blockIdx.y * 64;
    const int tid  = threadIdx.x;
    const int lane = tid & 31;
    const int w    = tid >> 5;
    const int wr   = w >> 1;                  // i-group 0..3
    const int wc   = w & 1;                   // d-half  0..1
    const int i    = tid >> 2;                // P-phase row 0..63
    const int quarter = tid & 3;              // P-phase 16-j group

    const int rowg = head * NN + i0 + i;
    const float si = g_ssrc[rowg];
    const float Ei = g_E[rowg];
    const float ei = g_e[rowg];
    const float* tB = g_sdst + head * NN;
    const float* FB = g_F + head * NN;
    const float* fB = g_f + head * NN;
    const unsigned* mrow = g_adjm + (size_t)(i0 + i) * NW;
    const float* hT = g_hT + (size_t)head * DHH * NN;

    // cp.async B-tile chunk assignment: 1024 float4 per tile, 4 per thread
    const int brow = tid >> 4;                // base row (d) for r=0
    const int bc4  = tid & 15;

    // ldmatrix addresses (pitch 68 words; 68 mod 32 = 4 -> conflict-free)
    const uint32_t sPu = smem_u32(sP);
    const uint32_t sBu = smem_u32(sB);
    const uint32_t aAddr = sPu +
        (((wr * 16 + (lane & 15)) * PITCH + (lane >> 4) * 4) << 2);
    const uint32_t bAddr0 = sBu +
        ((((lane >> 4) * 8 + (lane & 7) + wc * 32) * PITCH +
          ((lane & 8) ? 4 : 0)) << 2);

    float c[4][4] = {};
    float rs = 0.f;

    // ---- preload B tile 0 ----
#pragma unroll
    for (int r = 0; r < 4; r++) {
        int row = brow + r * 16;
        uint32_t dst = sBu + ((row * PITCH + bc4 * 4) << 2);
        CP_ASYNC16(dst, hT + (size_t)row * NN + bc4 * 4);
    }
    CP_COMMIT();

    for (int t = 0; t < NT; t++) {
        const int buf = t & 1;
        // ---- prefetch B tile t+1 into other buffer ----
        if (t + 1 < NT) {
            const int j1 = (t + 1) * TJ;
            const uint32_t bb = sBu + (((buf ^ 1) * 64 * PITCH) << 2);
#pragma unroll
            for (int r = 0; r < 4; r++) {
                int row = brow + r * 16;
                uint32_t dst = bb + ((row * PITCH + bc4 * 4) << 2);
                CP_ASYNC16(dst, hT + (size_t)row * NN + j1 + bc4 * 4);
            }
        }
        CP_COMMIT();

        // ---- P tile: 16 entries per thread (separable exp + bitmask) ----
        const int j0 = t * TJ;
        const unsigned m = mrow[t * 2 + (quarter >> 1)] >> ((quarter & 1) * 16);
        float* prow = sP + i * PITCH + quarter * 16;
#pragma unroll
        for (int q = 0; q < 4; q++) {
            const int jb = j0 + quarter * 16 + q * 4;
            float4 tv = *(const float4*)(tB + jb);
            float4 Fv = *(const float4*)(FB + jb);
            float4 fv = *(const float4*)(fB + jb);
            float p0 = (si + tv.x) > 0.f ? Ei * Fv.x : ei * fv.x;
            float p1 = (si + tv.y) > 0.f ? Ei * Fv.y : ei * fv.y;
            float p2 = (si + tv.z) > 0.f ? Ei * Fv.z : ei * fv.z;
            float p3 = (si + tv.w) > 0.f ? Ei * Fv.w : ei * fv.w;
            p0 = (m >> (q * 4 + 0)) & 1u ? p0 : 0.f;
            p1 = (m >> (q * 4 + 1)) & 1u ? p1 : 0.f;
            p2 = (m >> (q * 4 + 2)) & 1u ? p2 : 0.f;
            p3 = (m >> (q * 4 + 3)) & 1u ? p3 : 0.f;
            rs += p0 + p1 + p2 + p3;
            uint4 u = make_uint4(f2tf(p0), f2tf(p1), f2tf(p2), f2tf(p3));
            *(uint4*)(prow + q * 4) = u;
        }

        // wait for B tile t (allow 1 outstanding = tile t+1), then barrier
        if (t + 1 < NT) { CP_WAIT(1); } else { CP_WAIT(0); }
        __syncthreads();

        // ---- tensor phase: 8 k-steps x 4 n-tiles of m16n8k8 ----
        const uint32_t bA = bAddr0 + ((buf * 64 * PITCH) << 2);
#pragma unroll
        for (int ks = 0; ks < 8; ks++) {
            uint32_t a0, a1, a2, a3;
            LDSM4(a0, a1, a2, a3, aAddr + ks * 32);
#pragma unroll
            for (int q2 = 0; q2 < 2; q2++) {
                uint32_t b0, b1, b2, b3;
                LDSM4(b0, b1, b2, b3, bA + q2 * (16 * PITCH * 4) + ks * 32);
                MMA_TF32(c[2 * q2],     a0, a1, a2, a3, b0, b1);
                MMA_TF32(c[2 * q2 + 1], a0, a1, a2, a3, b2, b3);
            }
        }
        __syncthreads();   // protect sP before next tile's P writes
    }

    // ---- rowsums: reduce over the 4 threads sharing row i ----
    rs += __shfl_xor_sync(0xffffffffu, rs, 1);
    rs += __shfl_xor_sync(0xffffffffu, rs, 2);
    if (quarter == 0) sRS[i] = rs;
    __syncthreads();

    // ---- epilogue: normalize + ELU + store ----
    const int g  = lane >> 2;
    const int tg = lane & 3;
    const float inv0 = 1.0f / sRS[wr * 16 + g];
    const float inv1 = 1.0f / sRS[wr * 16 + g + 8];
    float* o0 = out + (size_t)(i0 + wr * 16 + g) * (NH * DHH) + head * DHH + wc * 32;
    float* o1 = o0 + (size_t)8 * (NH * DHH);
#pragma unroll
    for (int nt = 0; nt < 4; nt++) {
        float v0 = c[nt][0] * inv0;
        float v1 = c[nt][1] * inv0;
        float v2 = c[nt][2] * inv1;
        float v3 = c[nt][3] * inv1;
        v0 = v0 > 0.f ? v0 : expm1f(v0);
        v1 = v1 > 0.f ? v1 : expm1f(v1);
        v2 = v2 > 0.f ? v2 : expm1f(v2);
        v3 = v3 > 0.f ? v3 : expm1f(v3);
        *(float2*)(o0 + nt * 8 + 2 * tg) = make_float2(v0, v1);
        *(float2*)(o1 + nt * 8 + 2 * tg) = make_float2(v2, v3);
    }
}

// ---------------------------------------------------------------------------
extern "C" void kernel_launch(void* const* d_in, const int* in_sizes, int n_in,
                              void* d_out, int out_size) {
    (void)in_sizes; (void)n_in; (void)out_size;
    const float* x   = (const float*)d_in[0];
    const int*   adj = (const int*)d_in[1];
    const float* W   = (const float*)d_in[2];
    const float* a   = (const float*)d_in[3];
    float* out = (float*)d_out;

    static bool attr_set = false;
    if (!attr_set) {
        cudaFuncSetAttribute(k3_agg, cudaFuncAttributeMaxDynamicSharedMemorySize,
                             SMEM3);
        attr_set = true;
    }

    k0_pack <<<NN * NW / 256, 256>>>(adj);
    k1_hproj<<<dim3(NH, NN / 64), 256>>>(x, W);
    k2_scores<<<dim3(NH, NN / 8), 256>>>(a);
    k3_agg  <<<dim3(NH, NN / 64), 256, SMEM3>>>(out);
}

// round 5
// speedup vs baseline: 7.3920x; 1.2065x over previous
#include <cuda_runtime.h>
#include <cstdint>

#define NN   4096
#define FIN  256
#define NH   4
#define DHH  64
#define NW   (NN / 32)      // 128 adj-mask words per row

// ------------------------- device globals (no alloc allowed) ---------------
__device__ float g_h [NH * NN * DHH];     // h[head][n][d]
__device__ float g_hT[NH * DHH * NN];     // hT[head][d][n], tf32-rounded
__device__ float g_ssrc[NH * NN];
__device__ float g_sdst[NH * NN];
__device__ float g_E[NH * NN];            // exp(s_src)
__device__ float g_e[NH * NN];            // exp(0.01*s_src)
__device__ float g_F[NH * NN];            // exp(s_dst)
__device__ float g_f[NH * NN];            // exp(0.01*s_dst)
__device__ unsigned g_adjm[NN * NW];      // adjacency bitmask

// ------------------------- helpers -----------------------------------------
__device__ __forceinline__ uint32_t smem_u32(const void* p) {
    uint32_t a;
    asm("{ .reg .u64 t; cvta.to.shared.u64 t, %1; cvt.u32.u64 %0, t; }"
        : "=r"(a) : "l"(p));
    return a;
}
__device__ __forceinline__ uint32_t f2tf(float x) {
    uint32_t u;
    asm("cvt.rna.tf32.f32 %0, %1;" : "=r"(u) : "f"(x));
    return u;
}
#define LDSM4(r0, r1, r2, r3, addr) \
    asm volatile("ldmatrix.sync.aligned.m8n8.x4.shared.b16 {%0,%1,%2,%3}, [%4];" \
                 : "=r"(r0), "=r"(r1), "=r"(r2), "=r"(r3) : "r"(addr))
#define MMA_TF32(c, a0, a1, a2, a3, b0, b1) \
    asm volatile("mma.sync.aligned.m16n8k8.row.col.f32.tf32.tf32.f32 " \
                 "{%0,%1,%2,%3}, {%4,%5,%6,%7}, {%8,%9}, {%0,%1,%2,%3};" \
                 : "+f"((c)[0]), "+f"((c)[1]), "+f"((c)[2]), "+f"((c)[3]) \
                 : "r"(a0), "r"(a1), "r"(a2), "r"(a3), "r"(b0), "r"(b1))
#define CP_ASYNC16(dst, src) \
    asm volatile("cp.async.cg.shared.global [%0], [%1], 16;" \
                 :: "r"(dst), "l"(src) : "memory")
#define CP_ASYNC8(dst, src) \
    asm volatile("cp.async.ca.shared.global [%0], [%1], 8;" \
                 :: "r"(dst), "l"(src) : "memory")
#define CP_COMMIT() asm volatile("cp.async.commit_group;" ::: "memory")
#define CP_WAIT(n)  asm volatile("cp.async.wait_group %0;" :: "n"(n) : "memory")

// ---------------------------------------------------------------------------
// Kernel 0: pack adj into bitmask words.
// ---------------------------------------------------------------------------
__global__ __launch_bounds__(256) void k0_pack(const int* __restrict__ adj) {
    const int widx = blockIdx.x * 256 + threadIdx.x;
    const int* p = adj + (size_t)widx * 32;
    unsigned m = 0;
#pragma unroll
    for (int q = 0; q < 8; q++) {
        int4 v = *(const int4*)(p + q * 4);
        m |= (v.x ? 1u : 0u) << (q * 4 + 0);
        m |= (v.y ? 1u : 0u) << (q * 4 + 1);
        m |= (v.z ? 1u : 0u) << (q * 4 + 2);
        m |= (v.w ? 1u : 0u) << (q * 4 + 3);
    }
    g_adjm[widx] = m;
}

// ---------------------------------------------------------------------------
// Kernel 1: h = x @ W per head; hT stored tf32-rounded.
// ---------------------------------------------------------------------------
__global__ __launch_bounds__(256) void k1_hproj(const float* __restrict__ x,
                                                const float* __restrict__ W) {
    __shared__ float xs[64][68];
    __shared__ float ws[64][68];
    const int head = blockIdx.x;
    const int n0   = blockIdx.y * 64;
    const int tid  = threadIdx.x;
    const int tx   = tid & 15;
    const int ty   = tid >> 4;
    const float* Wh = W + (size_t)head * FIN * DHH;

    float c[4][4] = {};
    for (int f0 = 0; f0 < FIN; f0 += 64) {
        __syncthreads();
#pragma unroll
        for (int r = 0; r < 4; r++) {
            int idx = tid + r * 256;
            int row = idx >> 4;
            int c4  = idx & 15;
            float4 v = *(const float4*)(x + (size_t)(n0 + row) * FIN + f0 + c4 * 4);
            xs[c4 * 4 + 0][row] = v.x;
            xs[c4 * 4 + 1][row] = v.y;
            xs[c4 * 4 + 2][row] = v.z;
            xs[c4 * 4 + 3][row] = v.w;
            *(float4*)&ws[row][c4 * 4] =
                *(const float4*)(Wh + (size_t)(f0 + row) * DHH + c4 * 4);
        }
        __syncthreads();
#pragma unroll 16
        for (int k = 0; k < 64; k++) {
            float4 av = *(const float4*)&xs[k][ty * 4];
            float4 bv = *(const float4*)&ws[k][tx * 4];
            const float aa[4] = {av.x, av.y, av.z, av.w};
            const float bb[4] = {bv.x, bv.y, bv.z, bv.w};
#pragma unroll
            for (int ii = 0; ii < 4; ii++)
#pragma unroll
                for (int jj = 0; jj < 4; jj++)
                    c[ii][jj] = fmaf(aa[ii], bb[jj], c[ii][jj]);
        }
    }
    float* hout = g_h + ((size_t)head * NN + n0) * DHH;
#pragma unroll
    for (int ii = 0; ii < 4; ii++)
        *(float4*)(hout + (size_t)(ty * 4 + ii) * DHH + tx * 4) =
            make_float4(c[ii][0], c[ii][1], c[ii][2], c[ii][3]);
    float* htb = g_hT + ((size_t)head * DHH) * NN + n0 + ty * 4;
#pragma unroll
    for (int jj = 0; jj < 4; jj++) {
        uint4 u = make_uint4(f2tf(c[0][jj]), f2tf(c[1][jj]),
                             f2tf(c[2][jj]), f2tf(c[3][jj]));
        *(uint4*)(htb + (size_t)(tx * 4 + jj) * NN) = u;
    }
}

// ---------------------------------------------------------------------------
// Kernel 2: scores + separable-exp tables.
// ---------------------------------------------------------------------------
__global__ __launch_bounds__(256) void k2_scores(const float* __restrict__ a) {
    const int head = blockIdx.x;
    const int lane = threadIdx.x & 31;
    const int warp = threadIdx.x >> 5;
    const int n    = blockIdx.y * 8 + warp;
    const float* hv = g_h + ((size_t)head * NN + n) * DHH;
    const float* ah = a + head * 2 * DHH;
    float h0 = hv[lane], h1 = hv[lane + 32];
    float s1 = h0 * ah[lane]      + h1 * ah[lane + 32];
    float s2 = h0 * ah[64 + lane] + h1 * ah[96 + lane];
#pragma unroll
    for (int o = 16; o; o >>= 1) {
        s1 += __shfl_xor_sync(0xffffffffu, s1, o);
        s2 += __shfl_xor_sync(0xffffffffu, s2, o);
    }
    if (lane == 0) {
        const int idx = head * NN + n;
        g_ssrc[idx] = s1;
        g_sdst[idx] = s2;
        g_E[idx] = __expf(s1);
        g_e[idx] = __expf(0.01f * s1);
        g_F[idx] = __expf(s2);
        g_f[idx] = __expf(0.01f * s2);
    }
}

// ---------------------------------------------------------------------------
// Kernel 3: masked-softmax aggregation + ELU via mma.sync tf32.
// 128 threads = 4 warps, each 32i x 32d.  TI=64 rows/CTA, j-tiles of 64.
// cp.async double-buffers: B tile, t/F/f vectors, adj mask words.
// ---------------------------------------------------------------------------
#define TJ 64
#define NT (NN / TJ)
#define PITCH 68
// dynamic smem layout (float offsets)
#define SP_OFF  0                              // sP[64][68]
#define SB_OFF  (64 * PITCH)                   // sB[2][64][68]
#define ST_OFF  (SB_OFF + 2 * 64 * PITCH)      // sT[2][3][64]
#define SM_OFF  (ST_OFF + 2 * 3 * 64)          // sM[2][128] (uint)
#define RS_OFF  (SM_OFF + 2 * 128)
#define SMEM3   ((RS_OFF + 64) * 4)            // 55040 bytes

__global__ __launch_bounds__(128, 4) void k3_agg(float* __restrict__ out) {
    extern __shared__ float dsm[];
    float*    sP  = dsm + SP_OFF;
    float*    sB  = dsm + SB_OFF;
    float*    sT  = dsm + ST_OFF;
    unsigned* sM  = (unsigned*)(dsm + SM_OFF);
    float*    sRS = dsm + RS_OFF;

    const int head = blockIdx.x;
    const int i0   = blockIdx.y * 64;
    const int tid  = threadIdx.x;
    const int lane = tid & 31;
    const int w    = tid >> 5;
    const int wr   = w >> 1;                  // 32-row group 0..1
    const int wc   = w & 1;                   // 32-d  group 0..1
    const int i    = tid >> 1;                // P-phase row 0..63
    const int half = tid & 1;                 // P-phase j-half (32 j)

    const int rowg = head * NN + i0 + i;
    const float si = g_ssrc[rowg];
    const float Ei = g_E[rowg];
    const float ei = g_e[rowg];
    const float* tB = g_sdst + head * NN;
    const float* FB = g_F + head * NN;
    const float* fB = g_f + head * NN;
    const float* hT = g_hT + (size_t)head * DHH * NN;

    const uint32_t sPu = smem_u32(sP);
    const uint32_t sBu = smem_u32(sB);
    const uint32_t sTu = smem_u32(sT);
    const uint32_t sMu = smem_u32(sM);

    // B-tile cp.async: 1024 float4, 8 per thread
    const int brow = tid >> 4;                // + r*8
    const int bc4  = tid & 15;
    // sT cp.async: 48 float4 (t/F/f), threads 0..47
    const int ta  = tid >> 4;                 // array 0..2
    const int tc4 = tid & 15;
    const float* tsrc = (ta == 0 ? tB : (ta == 1 ? FB : fB)) + tc4 * 4;

    // ldmatrix base addresses (pitch 68 words, conflict-free)
    const uint32_t aAddr = sPu +
        (((wr * 32 + (lane & 15)) * PITCH + (lane >> 4) * 4) << 2);
    const uint32_t bAddr0 = sBu +
        ((((lane >> 4) * 8 + (lane & 7) + wc * 32) * PITCH +
          ((lane & 8) ? 4 : 0)) << 2);

    float c[8][4] = {};
    float rs = 0.f;

    // ---- preload tile 0 into buffer 0 ----
#pragma unroll
    for (int r = 0; r < 8; r++) {
        int row = brow + r * 8;
        CP_ASYNC16(sBu + ((row * PITCH + bc4 * 4) << 2),
                   hT + (size_t)row * NN + bc4 * 4);
    }
    if (tid < 48) CP_ASYNC16(sTu + ((ta * 64 + tc4 * 4) << 2), tsrc);
    if (tid < 64) CP_ASYNC8(sMu + ((tid * 2) << 2),
                            g_adjm + (size_t)(i0 + tid) * NW);
    CP_COMMIT();

    for (int t = 0; t < NT; t++) {
        const int buf = t & 1;
        // ---- prefetch tile t+1 into other buffer ----
        if (t + 1 < NT) {
            const int j1 = (t + 1) * TJ;
            const uint32_t bb = sBu + (((buf ^ 1) * 64 * PITCH) << 2);
#pragma unroll
            for (int r = 0; r < 8; r++) {
                int row = brow + r * 8;
                CP_ASYNC16(bb + ((row * PITCH + bc4 * 4) << 2),
                           hT + (size_t)row * NN + j1 + bc4 * 4);
            }
            if (tid < 48)
                CP_ASYNC16(sTu + (((buf ^ 1) * 192 + ta * 64 + tc4 * 4) << 2),
                           tsrc + j1);
            if (tid < 64)
                CP_ASYNC8(sMu + (((buf ^ 1) * 128 + tid * 2) << 2),
                          g_adjm + (size_t)(i0 + tid) * NW + (t + 1) * 2);
        }
        CP_COMMIT();
        CP_WAIT(1);
        __syncthreads();   // tile t async data visible; prev MMA done (sP free)

        // ---- P phase: 32 entries per thread from smem-staged t/F/f ----
        const float* sTb = sT + buf * 192;
        const unsigned m = sM[buf * 128 + i * 2 + half];
        float* prow = sP + i * PITCH + half * 32;
#pragma unroll
        for (int q = 0; q < 8; q++) {
            const int jb = half * 32 + q * 4;
            float4 tv = *(const float4*)(sTb + jb);
            float4 Fv = *(const float4*)(sTb + 64 + jb);
            float4 fv = *(const float4*)(sTb + 128 + jb);
            float p0 = (si + tv.x) > 0.f ? Ei * Fv.x : ei * fv.x;
            float p1 = (si + tv.y) > 0.f ? Ei * Fv.y : ei * fv.y;
            float p2 = (si + tv.z) > 0.f ? Ei * Fv.z : ei * fv.z;
            float p3 = (si + tv.w) > 0.f ? Ei * Fv.w : ei * fv.w;
            p0 = (m >> (q * 4 + 0)) & 1u ? p0 : 0.f;
            p1 = (m >> (q * 4 + 1)) & 1u ? p1 : 0.f;
            p2 = (m >> (q * 4 + 2)) & 1u ? p2 : 0.f;
            p3 = (m >> (q * 4 + 3)) & 1u ? p3 : 0.f;
            rs += p0 + p1 + p2 + p3;
            uint4 u = make_uint4(f2tf(p0), f2tf(p1), f2tf(p2), f2tf(p3));
            *(uint4*)(prow + q * 4) = u;
        }
        __syncthreads();

        // ---- tensor phase: 8 k-steps, warp tile 32i x 32d ----
        const uint32_t bA = bAddr0 + ((buf * 64 * PITCH) << 2);
#pragma unroll
        for (int ks = 0; ks < 8; ks++) {
            uint32_t a0, a1, a2, a3, a4, a5, a6, a7;
            LDSM4(a0, a1, a2, a3, aAddr + ks * 32);
            LDSM4(a4, a5, a6, a7, aAddr + (16 * PITCH * 4) + ks * 32);
#pragma unroll
            for (int q2 = 0; q2 < 2; q2++) {
                uint32_t b0, b1, b2, b3;
                LDSM4(b0, b1, b2, b3, bA + q2 * (16 * PITCH * 4) + ks * 32);
                MMA_TF32(c[q2 * 2],     a0, a1, a2, a3, b0, b1);
                MMA_TF32(c[q2 * 2 + 1], a0, a1, a2, a3, b2, b3);
                MMA_TF32(c[4 + q2 * 2],     a4, a5, a6, a7, b0, b1);
                MMA_TF32(c[4 + q2 * 2 + 1], a4, a5, a6, a7, b2, b3);
            }
        }
    }

    // ---- rowsums: lanes 2k/2k+1 share row i ----
    rs += __shfl_xor_sync(0xffffffffu, rs, 1);
    if (half == 0) sRS[i] = rs;
    __syncthreads();

    // ---- epilogue: normalize + ELU + store ----
#pragma unroll
    for (int mi = 0; mi < 2; mi++) {
        const int r0 = wr * 32 + mi * 16 + (lane >> 2);
        const float invA = 1.0f / sRS[r0];
        const float invB = 1.0f / sRS[r0 + 8];
        float* oA = out + (size_t)(i0 + r0) * (NH * DHH) + head * DHH +
                    wc * 32 + (lane & 3) * 2;
        float* oB = oA + (size_t)8 * (NH * DHH);
#pragma unroll
        for (int q2 = 0; q2 < 2; q2++)
#pragma unroll
            for (int nn = 0; nn < 2; nn++) {
                const float* cf = c[mi * 4 + q2 * 2 + nn];
                float v0 = cf[0] * invA;
                float v1 = cf[1] * invA;
                float v2 = cf[2] * invB;
                float v3 = cf[3] * invB;
                v0 = v0 > 0.f ? v0 : expm1f(v0);
                v1 = v1 > 0.f ? v1 : expm1f(v1);
                v2 = v2 > 0.f ? v2 : expm1f(v2);
                v3 = v3 > 0.f ? v3 : expm1f(v3);
                const int dof = q2 * 16 + nn * 8;
                *(float2*)(oA + dof) = make_float2(v0, v1);
                *(float2*)(oB + dof) = make_float2(v2, v3);
            }
    }
}

// ---------------------------------------------------------------------------
extern "C" void kernel_launch(void* const* d_in, const int* in_sizes, int n_in,
                              void* d_out, int out_size) {
    (void)in_sizes; (void)n_in; (void)out_size;
    const float* x   = (const float*)d_in[0];
    const int*   adj = (const int*)d_in[1];
    const float* W   = (const float*)d_in[2];
    const float* a   = (const float*)d_in[3];
    float* out = (float*)d_out;

    static bool attr_set = false;
    if (!attr_set) {
        cudaFuncSetAttribute(k3_agg, cudaFuncAttributeMaxDynamicSharedMemorySize,
                             SMEM3);
        attr_set = true;
    }

    k0_pack <<<NN * NW / 256, 256>>>(adj);
    k1_hproj<<<dim3(NH, NN / 64), 256>>>(x, W);
    k2_scores<<<dim3(NH, NN / 8), 256>>>(a);
    k3_agg  <<<dim3(NH, NN / 64), 128, SMEM3>>>(out);
}

// round 6
// speedup vs baseline: 10.7972x; 1.4607x over previous
#include <cuda_runtime.h>
#include <cuda_fp16.h>
#include <cstdint>

#define NN   4096
#define FIN  256
#define NH   4
#define DHH  64
#define NW   (NN / 32)      // 128 adj-mask words per row
#define NSPLIT 2

// ------------------------- device globals (no alloc allowed) ---------------
__device__ float  g_h  [NH * NN * DHH];   // h[head][n][d] fp32
__device__ __half g_hTh[NH * DHH * NN];   // hT[head][d][n] fp16
__device__ float  g_ssrc[NH * NN];
__device__ float  g_E[NH * NN];           // exp(s_src)
__device__ float  g_e[NH * NN];           // exp(0.01*s_src)
__device__ __half g_t_h[NH * NN];         // s_dst (half)
__device__ __half g_F_h[NH * NN];         // exp(s_dst)
__device__ __half g_f_h[NH * NN];         // exp(0.01*s_dst)
__device__ unsigned g_adjm[NN * NW];      // adjacency bitmask
__device__ float  g_acc[NSPLIT * NH * NN * DHH];  // unnormalized partials
__device__ float  g_rsp[NSPLIT * NH * NN];        // rowsum partials

// ------------------------- helpers -----------------------------------------
__device__ __forceinline__ uint32_t smem_u32(const void* p) {
    uint32_t a;
    asm("{ .reg .u64 t; cvta.to.shared.u64 t, %1; cvt.u32.u64 %0, t; }"
        : "=r"(a) : "l"(p));
    return a;
}
__device__ __forceinline__ __half2 u2h(uint32_t u) {
    union { uint32_t u; __half2 h; } c; c.u = u; return c.h;
}
__device__ __forceinline__ uint32_t h2u(__half2 h) {
    union { uint32_t u; __half2 h; } c; c.h = h; return c.u;
}
#define LDSM4(r0, r1, r2, r3, addr) \
    asm volatile("ldmatrix.sync.aligned.m8n8.x4.shared.b16 {%0,%1,%2,%3}, [%4];" \
                 : "=r"(r0), "=r"(r1), "=r"(r2), "=r"(r3) : "r"(addr))
#define MMA_F16(c, a0, a1, a2, a3, b0, b1) \
    asm volatile("mma.sync.aligned.m16n8k16.row.col.f32.f16.f16.f32 " \
                 "{%0,%1,%2,%3}, {%4,%5,%6,%7}, {%8,%9}, {%0,%1,%2,%3};" \
                 : "+f"((c)[0]), "+f"((c)[1]), "+f"((c)[2]), "+f"((c)[3]) \
                 : "r"(a0), "r"(a1), "r"(a2), "r"(a3), "r"(b0), "r"(b1))
#define CP_ASYNC16(dst, src) \
    asm volatile("cp.async.cg.shared.global [%0], [%1], 16;" \
                 :: "r"(dst), "l"(src) : "memory")
#define CP_COMMIT() asm volatile("cp.async.commit_group;" ::: "memory")
#define CP_WAIT1()  asm volatile("cp.async.wait_group 1;" ::: "memory")

// ---------------------------------------------------------------------------
// Kernel 0: pack adj into bitmask words.
// ---------------------------------------------------------------------------
__global__ __launch_bounds__(256) void k0_pack(const int* __restrict__ adj) {
    const int widx = blockIdx.x * 256 + threadIdx.x;
    const int* p = adj + (size_t)widx * 32;
    unsigned m = 0;
#pragma unroll
    for (int q = 0; q < 8; q++) {
        int4 v = *(const int4*)(p + q * 4);
        m |= (v.x ? 1u : 0u) << (q * 4 + 0);
        m |= (v.y ? 1u : 0u) << (q * 4 + 1);
        m |= (v.z ? 1u : 0u) << (q * 4 + 2);
        m |= (v.w ? 1u : 0u) << (q * 4 + 3);
    }
    g_adjm[widx] = m;
}

// ---------------------------------------------------------------------------
// Kernel 1: h = x @ W per head; writes fp32 h and fp16 hT.
// ---------------------------------------------------------------------------
__global__ __launch_bounds__(256) void k1_hproj(const float* __restrict__ x,
                                                const float* __restrict__ W) {
    __shared__ float xs[64][68];
    __shared__ float ws[64][68];
    const int head = blockIdx.x;
    const int n0   = blockIdx.y * 64;
    const int tid  = threadIdx.x;
    const int tx   = tid & 15;
    const int ty   = tid >> 4;
    const float* Wh = W + (size_t)head * FIN * DHH;

    float c[4][4] = {};
    for (int f0 = 0; f0 < FIN; f0 += 64) {
        __syncthreads();
#pragma unroll
        for (int r = 0; r < 4; r++) {
            int idx = tid + r * 256;
            int row = idx >> 4;
            int c4  = idx & 15;
            float4 v = *(const float4*)(x + (size_t)(n0 + row) * FIN + f0 + c4 * 4);
            xs[c4 * 4 + 0][row] = v.x;
            xs[c4 * 4 + 1][row] = v.y;
            xs[c4 * 4 + 2][row] = v.z;
            xs[c4 * 4 + 3][row] = v.w;
            *(float4*)&ws[row][c4 * 4] =
                *(const float4*)(Wh + (size_t)(f0 + row) * DHH + c4 * 4);
        }
        __syncthreads();
#pragma unroll 16
        for (int k = 0; k < 64; k++) {
            float4 av = *(const float4*)&xs[k][ty * 4];
            float4 bv = *(const float4*)&ws[k][tx * 4];
            const float aa[4] = {av.x, av.y, av.z, av.w};
            const float bb[4] = {bv.x, bv.y, bv.z, bv.w};
#pragma unroll
            for (int ii = 0; ii < 4; ii++)
#pragma unroll
                for (int jj = 0; jj < 4; jj++)
                    c[ii][jj] = fmaf(aa[ii], bb[jj], c[ii][jj]);
        }
    }
    float* hout = g_h + ((size_t)head * NN + n0) * DHH;
#pragma unroll
    for (int ii = 0; ii < 4; ii++)
        *(float4*)(hout + (size_t)(ty * 4 + ii) * DHH + tx * 4) =
            make_float4(c[ii][0], c[ii][1], c[ii][2], c[ii][3]);
    // fp16 transposed copy: g_hTh[head][d][n]
    __half* htb = g_hTh + (size_t)head * DHH * NN + n0 + ty * 4;
#pragma unroll
    for (int jj = 0; jj < 4; jj++) {
        __half2 p0 = __floats2half2_rn(c[0][jj], c[1][jj]);
        __half2 p1 = __floats2half2_rn(c[2][jj], c[3][jj]);
        uint2 u = make_uint2(h2u(p0), h2u(p1));
        *(uint2*)(htb + (size_t)(tx * 4 + jj) * NN) = u;
    }
}

// ---------------------------------------------------------------------------
// Kernel 2: scores + separable-exp tables (row side fp32, col side fp16).
// ---------------------------------------------------------------------------
__global__ __launch_bounds__(256) void k2_scores(const float* __restrict__ a) {
    const int head = blockIdx.x;
    const int lane = threadIdx.x & 31;
    const int warp = threadIdx.x >> 5;
    const int n    = blockIdx.y * 8 + warp;
    const float* hv = g_h + ((size_t)head * NN + n) * DHH;
    const float* ah = a + head * 2 * DHH;
    float h0 = hv[lane], h1 = hv[lane + 32];
    float s1 = h0 * ah[lane]      + h1 * ah[lane + 32];
    float s2 = h0 * ah[64 + lane] + h1 * ah[96 + lane];
#pragma unroll
    for (int o = 16; o; o >>= 1) {
        s1 += __shfl_xor_sync(0xffffffffu, s1, o);
        s2 += __shfl_xor_sync(0xffffffffu, s2, o);
    }
    if (lane == 0) {
        const int idx = head * NN + n;
        g_ssrc[idx] = s1;
        g_E[idx] = __expf(s1);
        g_e[idx] = __expf(0.01f * s1);
        g_t_h[idx] = __float2half_rn(s2);
        g_F_h[idx] = __float2half_rn(__expf(s2));
        g_f_h[idx] = __float2half_rn(__expf(0.01f * s2));
    }
}

// ---------------------------------------------------------------------------
// Kernel 3: masked-softmax aggregation via mma.sync fp16 (fp32 accum).
// Grid (NH, NN/64, NSPLIT): CTA = 1 head x 64 i-rows x 2048-j slice.
// 128 threads = 4 warps, each 32i x 32d. j-tiles of 64, B double-buffered.
// Writes unnormalized partials; k4 combines+normalizes+ELU.
// ---------------------------------------------------------------------------
#define TJ 64
#define JRANGE (NN / NSPLIT)
#define NT (JRANGE / TJ)
#define PITCH 72   // halves; 144B rows -> conflict-free ldmatrix

__global__ __launch_bounds__(128, 4) void k3_agg() {
    __shared__ __align__(16) __half sP[64 * PITCH];       // 9216 B
    __shared__ __align__(16) __half sB[2][64 * PITCH];    // 18432 B

    const int head  = blockIdx.x;
    const int i0    = blockIdx.y * 64;
    const int split = blockIdx.z;
    const int jbase = split * JRANGE;
    const int tid   = threadIdx.x;
    const int lane  = tid & 31;
    const int w     = tid >> 5;
    const int wr    = w >> 1;                 // 32-row group
    const int wc    = w & 1;                  // 32-d group
    const int i     = tid >> 1;               // P-phase row 0..63
    const int jhalf = tid & 1;                // P-phase 32-j half

    const int rowg = head * NN + i0 + i;
    const __half2 nsi2 = __float2half2_rn(-g_ssrc[rowg]);
    const __half2 Ei2  = __float2half2_rn(g_E[rowg]);
    const __half2 ei2  = __float2half2_rn(g_e[rowg]);
    const __half2 cap2 = __float2half2_rn(60000.f);
    const __half* tp = g_t_h + head * NN;
    const __half* Fp = g_F_h + head * NN;
    const __half* fp = g_f_h + head * NN;
    const unsigned* mrow = g_adjm + (size_t)(i0 + i) * NW + (jbase >> 5) + jhalf;
    const __half* hTh = g_hTh + (size_t)head * DHH * NN;

    const uint32_t sPu = smem_u32(sP);
    const uint32_t sBu = smem_u32(sB);

    // ldmatrix lane address pieces: row = base + (lane&15), col16B = (lane>>4)
    const uint32_t lrow = lane & 15;
    const uint32_t lcol = (lane >> 4) * 8;    // halves
    const uint32_t aBase = sPu + ((wr * 32 + lrow) * PITCH + lcol) * 2;
    const uint32_t bBase = sBu + ((wc * 32 + lrow) * PITCH + lcol) * 2;

    float c[8][4] = {};
    float rs = 0.f;

    // ---- preload B tile 0 ----
#pragma unroll
    for (int k = 0; k < 4; k++) {
        int ch = tid + k * 128;               // 0..511
        int row = ch >> 3;
        int kc  = ch & 7;
        CP_ASYNC16(sBu + row * 144 + kc * 16,
                   hTh + (size_t)row * NN + jbase + kc * 8);
    }
    CP_COMMIT();

    for (int t = 0; t < NT; t++) {
        const int buf = t & 1;
        __syncthreads();   // all warps done with prev MMA: sP free, sB[buf^1] free

        // ---- prefetch B tile t+1 ----
        if (t + 1 < NT) {
            const int j1 = jbase + (t + 1) * TJ;
            const uint32_t bb = sBu + (buf ^ 1) * 9216;
#pragma unroll
            for (int k = 0; k < 4; k++) {
                int ch = tid + k * 128;
                int row = ch >> 3;
                int kc  = ch & 7;
                CP_ASYNC16(bb + row * 144 + kc * 16,
                           hTh + (size_t)row * NN + j1 + kc * 8);
            }
        }
        CP_COMMIT();       // empty group on last tile keeps wait-depth uniform

        // ---- P phase: 32 j per thread, half2 SIMD, direct LDG tables ----
        const int j0 = jbase + t * TJ;
        const unsigned m = mrow[t * 2];
        const uint4* tu = (const uint4*)(tp + j0 + jhalf * 32);
        const uint4* Fu = (const uint4*)(Fp + j0 + jhalf * 32);
        const uint4* fu = (const uint4*)(fp + j0 + jhalf * 32);
        const uint32_t pdst = sPu + i * 144 + jhalf * 64;
#pragma unroll
        for (int ch = 0; ch < 4; ch++) {
            uint4 tv = tu[ch], Fv = Fu[ch], fv = fu[ch];
            const uint32_t ta[4] = {tv.x, tv.y, tv.z, tv.w};
            const uint32_t Fa[4] = {Fv.x, Fv.y, Fv.z, Fv.w};
            const uint32_t fa[4] = {fv.x, fv.y, fv.z, fv.w};
            uint32_t vr[4];
#pragma unroll
            for (int u = 0; u < 4; u++) {
                __half2 cmp = __hgt2(u2h(ta[u]), nsi2);
                __half2 hiv = __hmul2(Ei2, u2h(Fa[u]));
                __half2 lov = __hmul2(ei2, u2h(fa[u]));
                __half2 v = __hfma2(cmp, __hsub2(hiv, lov), lov);
                v = __hmin2(v, cap2);            // guard inf before masking
                unsigned bb2 = (m >> (ch * 8 + u * 2)) & 3u;
                unsigned mm = ((bb2 & 1u) * 0x3C00u) | ((bb2 >> 1) * 0x3C000000u);
                v = __hmul2(v, u2h(mm));
                float2 vf = __half22float2(v);
                rs += vf.x + vf.y;
                vr[u] = h2u(v);
            }
            asm volatile("st.shared.v4.b32 [%0], {%1,%2,%3,%4};"
                         :: "r"(pdst + ch * 16), "r"(vr[0]), "r"(vr[1]),
                            "r"(vr[2]), "r"(vr[3]) : "memory");
        }

        CP_WAIT1();        // B tile t (older group) complete
        __syncthreads();   // sP + sB[buf] visible to all

        // ---- tensor phase: 4 k-steps (K=16), warp tile 32i x 32d ----
        const uint32_t bB = bBase + buf * 9216;
#pragma unroll
        for (int ks = 0; ks < 4; ks++) {
            uint32_t a0, a1, a2, a3, a4, a5, a6, a7;
            LDSM4(a0, a1, a2, a3, aBase + ks * 32);
            LDSM4(a4, a5, a6, a7, aBase + 16 * PITCH * 2 + ks * 32);
#pragma unroll
            for (int q2 = 0; q2 < 2; q2++) {
                uint32_t b0, b1, b2, b3;
                LDSM4(b0, b1, b2, b3, bB + q2 * (16 * PITCH * 2) + ks * 32);
                MMA_F16(c[q2 * 2 + 0], a0, a1, a2, a3, b0, b2);
                MMA_F16(c[q2 * 2 + 1], a0, a1, a2, a3, b1, b3);
                MMA_F16(c[4 + q2 * 2 + 0], a4, a5, a6, a7, b0, b2);
                MMA_F16(c[4 + q2 * 2 + 1], a4, a5, a6, a7, b1, b3);
            }
        }
    }

    // ---- rowsum partial: pair-reduce, write direct to global ----
    rs += __shfl_xor_sync(0xffffffffu, rs, 1);
    if (jhalf == 0)
        g_rsp[((size_t)split * NH + head) * NN + i0 + i] = rs;

    // ---- write unnormalized acc partial ----
    float* accb = g_acc + (((size_t)split * NH + head) * NN + i0) * DHH;
#pragma unroll
    for (int mi = 0; mi < 2; mi++) {
        const int r0 = wr * 32 + mi * 16 + (lane >> 2);
#pragma unroll
        for (int q2 = 0; q2 < 2; q2++)
#pragma unroll
            for (int nn2 = 0; nn2 < 2; nn2++) {
                const float* cf = c[mi * 4 + q2 * 2 + nn2];
                const int col = wc * 32 + q2 * 16 + nn2 * 8 + (lane & 3) * 2;
                *(float2*)(accb + (size_t)r0 * DHH + col) =
                    make_float2(cf[0], cf[1]);
                *(float2*)(accb + (size_t)(r0 + 8) * DHH + col) =
                    make_float2(cf[2], cf[3]);
            }
    }
}

// ---------------------------------------------------------------------------
// Kernel 4: combine split partials, normalize, ELU, store.
// ---------------------------------------------------------------------------
__global__ __launch_bounds__(256) void k4_fin(float* __restrict__ out) {
    const int n = blockIdx.x;
    const int tid = threadIdx.x;
    const int head = tid >> 6;
    const int d = tid & 63;
    const size_t a0 = (((size_t)0 * NH + head) * NN + n) * DHH + d;
    const size_t a1 = (((size_t)1 * NH + head) * NN + n) * DHH + d;
    float acc = g_acc[a0] + g_acc[a1];
    float r = g_rsp[((size_t)0 * NH + head) * NN + n] +
              g_rsp[((size_t)1 * NH + head) * NN + n];
    float v = acc / r;
    v = v > 0.f ? v : expm1f(v);
    out[(size_t)n * (NH * DHH) + head * DHH + d] = v;
}

// ---------------------------------------------------------------------------
extern "C" void kernel_launch(void* const* d_in, const int* in_sizes, int n_in,
                              void* d_out, int out_size) {
    (void)in_sizes; (void)n_in; (void)out_size;
    const float* x   = (const float*)d_in[0];
    const int*   adj = (const int*)d_in[1];
    const float* W   = (const float*)d_in[2];
    const float* a   = (const float*)d_in[3];
    float* out = (float*)d_out;

    k0_pack  <<<NN * NW / 256, 256>>>(adj);
    k1_hproj <<<dim3(NH, NN / 64), 256>>>(x, W);
    k2_scores<<<dim3(NH, NN / 8), 256>>>(a);
    k3_agg   <<<dim3(NH, NN / 64, NSPLIT), 128>>>();
    k4_fin   <<<NN, 256>>>(out);
}

// round 7
// speedup vs baseline: 11.6438x; 1.0784x over previous
#include <cuda_runtime.h>
#include <cuda_fp16.h>
#include <cstdint>

#define NN   4096
#define FIN  256
#define NH   4
#define DHH  64
#define NW   (NN / 32)      // 128 adj-mask words per row
#define NSPLIT 2

// ------------------------- device globals (no alloc allowed) ---------------
__device__ __half g_hTh[NH * DHH * NN];   // hT[head][d][n] fp16
__device__ float  g_ssrc[NH * NN];
__device__ float  g_E[NH * NN];           // exp(s_src)
__device__ float  g_e[NH * NN];           // exp(0.01*s_src)
__device__ __half g_t_h[NH * NN];         // s_dst (half)
__device__ __half g_F_h[NH * NN];         // exp(s_dst)
__device__ __half g_f_h[NH * NN];         // exp(0.01*s_dst)
__device__ unsigned g_adjm[NN * NW];      // adjacency bitmask
__device__ float  g_acc[NSPLIT * NH * NN * DHH];  // unnormalized partials
__device__ float  g_rsp[NSPLIT * NH * NN];        // rowsum partials

// ------------------------- helpers -----------------------------------------
__device__ __forceinline__ uint32_t smem_u32(const void* p) {
    uint32_t a;
    asm("{ .reg .u64 t; cvta.to.shared.u64 t, %1; cvt.u32.u64 %0, t; }"
        : "=r"(a) : "l"(p));
    return a;
}
__device__ __forceinline__ __half2 u2h(uint32_t u) {
    union { uint32_t u; __half2 h; } c; c.u = u; return c.h;
}
__device__ __forceinline__ uint32_t h2u(__half2 h) {
    union { uint32_t u; __half2 h; } c; c.h = h; return c.u;
}
#define LDSM4(r0, r1, r2, r3, addr) \
    asm volatile("ldmatrix.sync.aligned.m8n8.x4.shared.b16 {%0,%1,%2,%3}, [%4];" \
                 : "=r"(r0), "=r"(r1), "=r"(r2), "=r"(r3) : "r"(addr))
#define MMA_F16(c, a0, a1, a2, a3, b0, b1) \
    asm volatile("mma.sync.aligned.m16n8k16.row.col.f32.f16.f16.f32 " \
                 "{%0,%1,%2,%3}, {%4,%5,%6,%7}, {%8,%9}, {%0,%1,%2,%3};" \
                 : "+f"((c)[0]), "+f"((c)[1]), "+f"((c)[2]), "+f"((c)[3]) \
                 : "r"(a0), "r"(a1), "r"(a2), "r"(a3), "r"(b0), "r"(b1))
#define CP_ASYNC16(dst, src) \
    asm volatile("cp.async.cg.shared.global [%0], [%1], 16;" \
                 :: "r"(dst), "l"(src) : "memory")
#define CP_COMMIT() asm volatile("cp.async.commit_group;" ::: "memory")
#define CP_WAIT1()  asm volatile("cp.async.wait_group 1;" ::: "memory")

// ---------------------------------------------------------------------------
// Kernel 0: pack adj into bitmask words — fully coalesced ballot-style.
// Thread reads int4 (16B, warp = 512B contiguous); 8-lane OR-reduce.
// ---------------------------------------------------------------------------
__global__ __launch_bounds__(256) void k0_pack(const int* __restrict__ adj) {
    const int t = blockIdx.x * 256 + threadIdx.x;       // int4 index
    int4 v = *(const int4*)(adj + (size_t)t * 4);
    unsigned nib = (v.x ? 1u : 0u) | (v.y ? 2u : 0u) |
                   (v.z ? 4u : 0u) | (v.w ? 8u : 0u);
    unsigned word = nib << ((t & 7) * 4);
    word |= __shfl_xor_sync(0xffffffffu, word, 1);
    word |= __shfl_xor_sync(0xffffffffu, word, 2);
    word |= __shfl_xor_sync(0xffffffffu, word, 4);
    if ((t & 7) == 0) g_adjm[t >> 3] = word;
}

// ---------------------------------------------------------------------------
// Kernel 1 (fused with old k2): h-tile = x @ W, write fp16 hT + score tables.
// CTA = 1 head x 32 n-rows (full d=64). 128 threads: tx(16)x ty(8), 4x4 tile.
// Epilogue: s1 = h.a1, s2 = h.a2 via smem reduction; E/e/t/F/f tables.
// ---------------------------------------------------------------------------
__global__ __launch_bounds__(128) void k1_fused(const float* __restrict__ x,
                                                const float* __restrict__ W,
                                                const float* __restrict__ a) {
    __shared__ float xs[64][36];    // [K][n] transposed x tile
    __shared__ float ws[64][68];    // [K][d]
    __shared__ float sr1[32][17];
    __shared__ float sr2[32][17];

    const int head = blockIdx.x;
    const int n0   = blockIdx.y * 32;
    const int tid  = threadIdx.x;
    const int tx   = tid & 15;      // d group (4 cols)
    const int ty   = tid >> 4;      // n group (4 rows)
    const float* Wh = W + (size_t)head * FIN * DHH;

    float c[4][4] = {};
    for (int f0 = 0; f0 < FIN; f0 += 64) {
        __syncthreads();
        // x tile 32n x 64K -> transposed into xs[K][n]
#pragma unroll
        for (int r = 0; r < 4; r++) {
            int idx = tid + r * 128;          // 512 float4 slots
            int row = idx >> 4;               // n 0..31
            int c4  = idx & 15;               // K quad
            float4 v = *(const float4*)(x + (size_t)(n0 + row) * FIN + f0 + c4 * 4);
            xs[c4 * 4 + 0][row] = v.x;
            xs[c4 * 4 + 1][row] = v.y;
            xs[c4 * 4 + 2][row] = v.z;
            xs[c4 * 4 + 3][row] = v.w;
        }
        // W tile 64K x 64d
#pragma unroll
        for (int r = 0; r < 8; r++) {
            int idx = tid + r * 128;          // 1024 float4 slots
            int row = idx >> 4;
            int c4  = idx & 15;
            *(float4*)&ws[row][c4 * 4] =
                *(const float4*)(Wh + (size_t)(f0 + row) * DHH + c4 * 4);
        }
        __syncthreads();
#pragma unroll 16
        for (int k = 0; k < 64; k++) {
            float4 av = *(const float4*)&xs[k][ty * 4];
            float4 bv = *(const float4*)&ws[k][tx * 4];
            const float aa[4] = {av.x, av.y, av.z, av.w};
            const float bb[4] = {bv.x, bv.y, bv.z, bv.w};
#pragma unroll
            for (int ii = 0; ii < 4; ii++)
#pragma unroll
                for (int jj = 0; jj < 4; jj++)
                    c[ii][jj] = fmaf(aa[ii], bb[jj], c[ii][jj]);
        }
    }

    // ---- fp16 transposed store: g_hTh[head][d][n0+ty*4 .. +3] ----
    __half* htb = g_hTh + (size_t)head * DHH * NN + n0 + ty * 4;
#pragma unroll
    for (int jj = 0; jj < 4; jj++) {
        __half2 p0 = __floats2half2_rn(c[0][jj], c[1][jj]);
        __half2 p1 = __floats2half2_rn(c[2][jj], c[3][jj]);
        uint2 u = make_uint2(h2u(p0), h2u(p1));
        *(uint2*)(htb + (size_t)(tx * 4 + jj) * NN) = u;
    }

    // ---- fused score epilogue ----
    const float4 a1v = *(const float4*)(a + head * 2 * DHH + tx * 4);
    const float4 a2v = *(const float4*)(a + head * 2 * DHH + DHH + tx * 4);
#pragma unroll
    for (int ii = 0; ii < 4; ii++) {
        float p1 = c[ii][0] * a1v.x + c[ii][1] * a1v.y +
                   c[ii][2] * a1v.z + c[ii][3] * a1v.w;
        float p2 = c[ii][0] * a2v.x + c[ii][1] * a2v.y +
                   c[ii][2] * a2v.z + c[ii][3] * a2v.w;
        sr1[ty * 4 + ii][tx] = p1;
        sr2[ty * 4 + ii][tx] = p2;
    }
    __syncthreads();
    if (tid < 32) {
        float s1 = 0.f, s2 = 0.f;
#pragma unroll
        for (int q = 0; q < 16; q++) { s1 += sr1[tid][q]; s2 += sr2[tid][q]; }
        const int idx = head * NN + n0 + tid;
        g_ssrc[idx] = s1;
        g_E[idx] = __expf(s1);
        g_e[idx] = __expf(0.01f * s1);
        g_t_h[idx] = __float2half_rn(s2);
        g_F_h[idx] = __float2half_rn(__expf(s2));
        g_f_h[idx] = __float2half_rn(__expf(0.01f * s2));
    }
}

// ---------------------------------------------------------------------------
// Kernel 3: masked-softmax aggregation via mma.sync fp16 (fp32 accum).
// Grid (NH, NN/64, NSPLIT). 128 threads = 4 warps, each 32i x 32d.
// ---------------------------------------------------------------------------
#define TJ 64
#define JRANGE (NN / NSPLIT)
#define NT (JRANGE / TJ)
#define PITCH 72   // halves; 144B rows -> conflict-free ldmatrix

__global__ __launch_bounds__(128, 4) void k3_agg() {
    __shared__ __align__(16) __half sP[64 * PITCH];       // 9216 B
    __shared__ __align__(16) __half sB[2][64 * PITCH];    // 18432 B

    const int head  = blockIdx.x;
    const int i0    = blockIdx.y * 64;
    const int split = blockIdx.z;
    const int jbase = split * JRANGE;
    const int tid   = threadIdx.x;
    const int lane  = tid & 31;
    const int w     = tid >> 5;
    const int wr    = w >> 1;
    const int wc    = w & 1;
    const int i     = tid >> 1;
    const int jhalf = tid & 1;

    const int rowg = head * NN + i0 + i;
    const __half2 nsi2 = __float2half2_rn(-g_ssrc[rowg]);
    const __half2 Ei2  = __float2half2_rn(g_E[rowg]);
    const __half2 ei2  = __float2half2_rn(g_e[rowg]);
    const __half2 cap2 = __float2half2_rn(60000.f);
    const __half* tp = g_t_h + head * NN;
    const __half* Fp = g_F_h + head * NN;
    const __half* fp = g_f_h + head * NN;
    const unsigned* mrow = g_adjm + (size_t)(i0 + i) * NW + (jbase >> 5) + jhalf;
    const __half* hTh = g_hTh + (size_t)head * DHH * NN;

    const uint32_t sPu = smem_u32(sP);
    const uint32_t sBu = smem_u32(sB);
    const uint32_t lrow = lane & 15;
    const uint32_t lcol = (lane >> 4) * 8;
    const uint32_t aBase = sPu + ((wr * 32 + lrow) * PITCH + lcol) * 2;
    const uint32_t bBase = sBu + ((wc * 32 + lrow) * PITCH + lcol) * 2;

    float c[8][4] = {};
    float rs = 0.f;

#pragma unroll
    for (int k = 0; k < 4; k++) {
        int ch = tid + k * 128;
        int row = ch >> 3;
        int kc  = ch & 7;
        CP_ASYNC16(sBu + row * 144 + kc * 16,
                   hTh + (size_t)row * NN + jbase + kc * 8);
    }
    CP_COMMIT();

    for (int t = 0; t < NT; t++) {
        const int buf = t & 1;
        __syncthreads();

        if (t + 1 < NT) {
            const int j1 = jbase + (t + 1) * TJ;
            const uint32_t bb = sBu + (buf ^ 1) * 9216;
#pragma unroll
            for (int k = 0; k < 4; k++) {
                int ch = tid + k * 128;
                int row = ch >> 3;
                int kc  = ch & 7;
                CP_ASYNC16(bb + row * 144 + kc * 16,
                           hTh + (size_t)row * NN + j1 + kc * 8);
            }
        }
        CP_COMMIT();

        const int j0 = jbase + t * TJ;
        const unsigned m = mrow[t * 2];
        const uint4* tu = (const uint4*)(tp + j0 + jhalf * 32);
        const uint4* Fu = (const uint4*)(Fp + j0 + jhalf * 32);
        const uint4* fu = (const uint4*)(fp + j0 + jhalf * 32);
        const uint32_t pdst = sPu + i * 144 + jhalf * 64;
#pragma unroll
        for (int ch = 0; ch < 4; ch++) {
            uint4 tv = tu[ch], Fv = Fu[ch], fv = fu[ch];
            const uint32_t ta[4] = {tv.x, tv.y, tv.z, tv.w};
            const uint32_t Fa[4] = {Fv.x, Fv.y, Fv.z, Fv.w};
            const uint32_t fa[4] = {fv.x, fv.y, fv.z, fv.w};
            uint32_t vr[4];
#pragma unroll
            for (int u = 0; u < 4; u++) {
                __half2 cmp = __hgt2(u2h(ta[u]), nsi2);
                __half2 hiv = __hmul2(Ei2, u2h(Fa[u]));
                __half2 lov = __hmul2(ei2, u2h(fa[u]));
                __half2 v = __hfma2(cmp, __hsub2(hiv, lov), lov);
                v = __hmin2(v, cap2);
                unsigned bb2 = (m >> (ch * 8 + u * 2)) & 3u;
                unsigned mm = ((bb2 & 1u) * 0x3C00u) | ((bb2 >> 1) * 0x3C000000u);
                v = __hmul2(v, u2h(mm));
                float2 vf = __half22float2(v);
                rs += vf.x + vf.y;
                vr[u] = h2u(v);
            }
            asm volatile("st.shared.v4.b32 [%0], {%1,%2,%3,%4};"
                         :: "r"(pdst + ch * 16), "r"(vr[0]), "r"(vr[1]),
                            "r"(vr[2]), "r"(vr[3]) : "memory");
        }

        CP_WAIT1();
        __syncthreads();

        const uint32_t bB = bBase + buf * 9216;
#pragma unroll
        for (int ks = 0; ks < 4; ks++) {
            uint32_t a0, a1, a2, a3, a4, a5, a6, a7;
            LDSM4(a0, a1, a2, a3, aBase + ks * 32);
            LDSM4(a4, a5, a6, a7, aBase + 16 * PITCH * 2 + ks * 32);
#pragma unroll
            for (int q2 = 0; q2 < 2; q2++) {
                uint32_t b0, b1, b2, b3;
                LDSM4(b0, b1, b2, b3, bB + q2 * (16 * PITCH * 2) + ks * 32);
                MMA_F16(c[q2 * 2 + 0], a0, a1, a2, a3, b0, b2);
                MMA_F16(c[q2 * 2 + 1], a0, a1, a2, a3, b1, b3);
                MMA_F16(c[4 + q2 * 2 + 0], a4, a5, a6, a7, b0, b2);
                MMA_F16(c[4 + q2 * 2 + 1], a4, a5, a6, a7, b1, b3);
            }
        }
    }

    rs += __shfl_xor_sync(0xffffffffu, rs, 1);
    if (jhalf == 0)
        g_rsp[((size_t)split * NH + head) * NN + i0 + i] = rs;

    float* accb = g_acc + (((size_t)split * NH + head) * NN + i0) * DHH;
#pragma unroll
    for (int mi = 0; mi < 2; mi++) {
        const int r0 = wr * 32 + mi * 16 + (lane >> 2);
#pragma unroll
        for (int q2 = 0; q2 < 2; q2++)
#pragma unroll
            for (int nn2 = 0; nn2 < 2; nn2++) {
                const float* cf = c[mi * 4 + q2 * 2 + nn2];
                const int col = wc * 32 + q2 * 16 + nn2 * 8 + (lane & 3) * 2;
                *(float2*)(accb + (size_t)r0 * DHH + col) =
                    make_float2(cf[0], cf[1]);
                *(float2*)(accb + (size_t)(r0 + 8) * DHH + col) =
                    make_float2(cf[2], cf[3]);
            }
    }
}

// ---------------------------------------------------------------------------
// Kernel 4: combine split partials, normalize, ELU, store.
// ---------------------------------------------------------------------------
__global__ __launch_bounds__(256) void k4_fin(float* __restrict__ out) {
    const int n = blockIdx.x;
    const int tid = threadIdx.x;
    const int head = tid >> 6;
    const int d = tid & 63;
    const size_t a0 = (((size_t)0 * NH + head) * NN + n) * DHH + d;
    const size_t a1 = (((size_t)1 * NH + head) * NN + n) * DHH + d;
    float acc = g_acc[a0] + g_acc[a1];
    float r = g_rsp[((size_t)0 * NH + head) * NN + n] +
              g_rsp[((size_t)1 * NH + head) * NN + n];
    float v = acc / r;
    v = v > 0.f ? v : expm1f(v);
    out[(size_t)n * (NH * DHH) + head * DHH + d] = v;
}

// ---------------------------------------------------------------------------
extern "C" void kernel_launch(void* const* d_in, const int* in_sizes, int n_in,
                              void* d_out, int out_size) {
    (void)in_sizes; (void)n_in; (void)out_size;
    const float* x   = (const float*)d_in[0];
    const int*   adj = (const int*)d_in[1];
    const float* W   = (const float*)d_in[2];
    const float* a   = (const float*)d_in[3];
    float* out = (float*)d_out;

    k0_pack  <<<NN * NN / 1024, 256>>>(adj);
    k1_fused <<<dim3(NH, NN / 32), 128>>>(x, W, a);
    k3_agg   <<<dim3(NH, NN / 64, NSPLIT), 128>>>();
    k4_fin   <<<NN, 256>>>(out);
}